// round 4
// baseline (speedup 1.0000x reference)
#include <cuda_runtime.h>
#include <cstdint>

#define NT 64
#define C 256
#define HW 3136
#define BM 128
#define BN 128
#define BK 32
#define KTILES 8

#define YROWB 144                       // 32 floats + 16B pad per Y row
#define SM_W0 0
#define SM_W1 16384
#define SM_Y0 32768
#define SM_Y1 (SM_Y0 + 128 * YROWB)
#define SMEM_BYTES (SM_Y1 + 128 * YROWB)   // 69632

// W in fragment order, tf32(RNA) bits: [half][kt][kk][mb][lane][r]
__device__ unsigned g_Wperm[C * C];

__device__ __forceinline__ unsigned f2tf32(float f) {
    unsigned r;
    asm("cvt.rna.tf32.f32 %0, %1;" : "=r"(r) : "f"(f));
    return r;
}
__device__ __forceinline__ unsigned smem_u32(const void* p) {
    return (unsigned)__cvta_generic_to_shared(p);
}
__device__ __forceinline__ void cp_async16(unsigned dst, const void* src) {
    asm volatile("cp.async.ca.shared.global [%0], [%1], 16;\n" :: "r"(dst), "l"(src));
}

// -------- prep: permute net_w into A-fragment register order (RNA tf32) ----
__global__ void prep_w_kernel(const float* __restrict__ net_w) {
    int idx  = blockIdx.x * 256 + threadIdx.x;      // 0..65535
    int r    = idx & 3;
    int lane = (idx >> 2) & 31;
    int mb   = (idx >> 7) & 7;
    int kk   = (idx >> 10) & 3;
    int kt   = (idx >> 12) & 7;
    int half = idx >> 15;
    int ar = lane >> 2, ac = lane & 3;
    int m = half * 128 + mb * 16 + ar + (r & 1) * 8;
    int k = kt * 32 + kk * 8 + ac + (r >> 1) * 4;
    g_Wperm[idx] = f2tf32(net_w[m * C + k]);
}

// -------- main fused kernel --------
__global__ __launch_bounds__(256, 2)
void msconv_kernel(const float* __restrict__ x, float* __restrict__ out) {
    extern __shared__ __align__(128) char smem[];
    const unsigned sb = smem_u32(smem);

    const int tid  = threadIdx.x;
    const int lane = tid & 31;
    const int wid  = tid >> 5;
    const int hw0  = blockIdx.x * BN;
    const int half = blockIdx.y;            // m0 = half*128
    const int z    = blockIdx.z;
    const int t    = z & 7;

    const int wm = (wid >> 2) * 64;
    const int wn = (wid & 3) * 32;
    const int ar = lane >> 2;
    const int ac = lane & 3;

    // producer constants: thread owns Y row pn, chunk half kp
    const int pn = tid & 127;
    const int kp = tid >> 7;                // 0/1: channels [kt*32+16kp, +16)
    const int hw = hw0 + pn;
    const bool ok = hw < HW;

    float acc[4][4][4];
#pragma unroll
    for (int i = 0; i < 4; ++i)
#pragma unroll
        for (int j = 0; j < 4; ++j)
#pragma unroll
            for (int k = 0; k < 4; ++k) acc[i][j][k] = 0.f;

    auto issueW = [&](int kt, unsigned wOff) {
        const unsigned* base = g_Wperm + ((half << 3) + kt) * 4096;
#pragma unroll
        for (int j = 0; j < 4; ++j) {
            int cidx = tid + 256 * j;       // 16B chunk index, linear copy
            cp_async16(sb + wOff + cidx * 16, base + cidx * 4);
        }
        asm volatile("cp.async.commit_group;\n" ::: "memory");
    };

    // fused temporal shift-sum into registers (4 chunks x 4 channels)
    auto produceY = [&](int kt, float yr[4][4]) {
        int base_c = kt * 32 + kp * 16;     // 16-aligned -> uniform taps
        int grp = base_c >> 6;
        int cg  = base_c & 63;
        int lo, hi;
        if (grp == 0 || cg >= 32) { lo = 0;    hi = 0;   }
        else if (cg < 16)         { lo = -grp; hi = -1;  }
        else                      { lo = 1;    hi = grp; }
#pragma unroll
        for (int a4 = 0; a4 < 4; ++a4) {
            float s0 = 0.f, s1 = 0.f, s2 = 0.f, s3 = 0.f;
            if (ok) {
                for (int dt = lo; dt <= hi; ++dt) {
                    int tt = t + dt;
                    if ((unsigned)tt < 8u) {
                        const float* xp =
                            x + ((size_t)(z + dt) * C + base_c + a4) * HW + hw;
                        s0 += xp[0];
                        s1 += xp[4 * HW];
                        s2 += xp[8 * HW];
                        s3 += xp[12 * HW];
                    }
                }
            }
            yr[a4][0] = s0; yr[a4][1] = s1; yr[a4][2] = s2; yr[a4][3] = s3;
        }
    };

    auto storeY = [&](unsigned yOff, const float yr[4][4]) {
#pragma unroll
        for (int a4 = 0; a4 < 4; ++a4) {
            uint4 s;
            s.x = f2tf32(yr[a4][0]); s.y = f2tf32(yr[a4][1]);
            s.z = f2tf32(yr[a4][2]); s.w = f2tf32(yr[a4][3]);
            *reinterpret_cast<uint4*>(
                smem + yOff + pn * YROWB + (2 * a4 + kp) * 16) = s;
        }
    };

    // ---- prologue ----
    {
        float yr[4][4];
        issueW(0, SM_W0);
        produceY(0, yr);
        storeY(SM_Y0, yr);
        asm volatile("cp.async.wait_group 0;\n" ::: "memory");
        __syncthreads();
    }

    float yreg[4][4];
    const int mbb = (wid >> 2) * 4;
    for (int kt = 0; kt < KTILES; ++kt) {
        const int cur = kt & 1;
        const unsigned wCur = cur ? SM_W1 : SM_W0;
        const unsigned yCur = cur ? SM_Y1 : SM_Y0;
        const unsigned wNxt = cur ? SM_W0 : SM_W1;
        const unsigned yNxt = cur ? SM_Y0 : SM_Y1;

        if (kt < KTILES - 1) {
            issueW(kt + 1, wNxt);
            produceY(kt + 1, yreg);
        }

        const char* wbuf = smem + wCur;
        const char* ybuf = smem + yCur;
#pragma unroll
        for (int P = 0; P < 2; ++P) {
            uint4 b[4];
#pragma unroll
            for (int ni = 0; ni < 4; ++ni) {
                int nn = wn + ni * 8 + ar;
                b[ni] = *reinterpret_cast<const uint4*>(
                    ybuf + nn * YROWB + ac * 32 + P * 16);
            }
#pragma unroll
            for (int k2 = 0; k2 < 2; ++k2) {
                int kk = P * 2 + k2;
                uint4 a[4];
#pragma unroll
                for (int mi = 0; mi < 4; ++mi) {
                    a[mi] = *reinterpret_cast<const uint4*>(
                        wbuf + ((kk * 8 + mbb + mi) * 32 + lane) * 16);
                }
#pragma unroll
                for (int mi = 0; mi < 4; ++mi)
#pragma unroll
                    for (int ni = 0; ni < 4; ++ni) {
                        unsigned b0 = k2 ? b[ni].z : b[ni].x;
                        unsigned b1 = k2 ? b[ni].w : b[ni].y;
                        asm volatile(
                            "mma.sync.aligned.m16n8k8.row.col.f32.tf32.tf32.f32 "
                            "{%0,%1,%2,%3}, {%4,%5,%6,%7}, {%8,%9}, {%0,%1,%2,%3};\n"
                            : "+f"(acc[mi][ni][0]), "+f"(acc[mi][ni][1]),
                              "+f"(acc[mi][ni][2]), "+f"(acc[mi][ni][3])
                            : "r"(a[mi].x), "r"(a[mi].y),
                              "r"(a[mi].z), "r"(a[mi].w),
                              "r"(b0), "r"(b1));
                    }
            }
        }

        if (kt < KTILES - 1) {
            storeY(yNxt, yreg);
            asm volatile("cp.async.wait_group 0;\n" ::: "memory");
            __syncthreads();
        }
    }

    // ---- epilogue: direct register -> gmem (float2), full coverage ----
    const int r  = lane >> 2;
    const int c2 = (lane & 3) * 2;
    const int m0 = half * BM;
#pragma unroll
    for (int mi = 0; mi < 4; ++mi) {
#pragma unroll
        for (int ni = 0; ni < 4; ++ni) {
            int co  = m0 + wm + mi * 16 + r;
            int hwo = hw0 + wn + ni * 8 + c2;
            if (hwo < HW) {
                float2 v0 = make_float2(acc[mi][ni][0], acc[mi][ni][1]);
                float2 v1 = make_float2(acc[mi][ni][2], acc[mi][ni][3]);
                *reinterpret_cast<float2*>(
                    out + ((size_t)z * C + co) * HW + hwo) = v0;
                *reinterpret_cast<float2*>(
                    out + ((size_t)z * C + co + 8) * HW + hwo) = v1;
            }
        }
    }
}

extern "C" void kernel_launch(void* const* d_in, const int* in_sizes, int n_in,
                              void* d_out, int out_size) {
    const float* x     = (const float*)d_in[0];
    const float* net_w = (const float*)d_in[5];
    float* out = (float*)d_out;

    static bool attr_done = false;
    if (!attr_done) {
        cudaFuncSetAttribute(msconv_kernel,
                             cudaFuncAttributeMaxDynamicSharedMemorySize,
                             SMEM_BYTES);
        attr_done = true;
    }

    prep_w_kernel<<<256, 256>>>(net_w);
    dim3 grid((HW + BN - 1) / BN, C / BM, NT);   // 25 x 2 x 64
    msconv_kernel<<<grid, 256, SMEM_BYTES>>>(x, out);
}